// round 1
// baseline (speedup 1.0000x reference)
#include <cuda_runtime.h>

// DynamicUpsamplingFilter:
//   x:       (4, 3, 180, 320) f32
//   filters: (4, 25, 16, 180, 320) f32
//   out:     (4, 48, 180, 320) f32
//   out[n, c*16+u, h, w] = sum_p x_pad[n, c, h+p/5-2, w+p%5-2] * filters[n, p, u, h, w]

#define NN 4
#define CC 3
#define HH 180
#define WW 320
#define UU 16
#define KH 5
#define KW 5
#define PP (KH*KW)
#define TILE_W 64
#define SROW 68   // TILE_W + 4 (halo) ... positions 0..67

__global__ void duf_kernel(const float* __restrict__ x,
                           const float* __restrict__ filters,
                           float* __restrict__ out) {
    // Block: one (n, h, w-tile of 64). 256 threads = 16 u-values x 16 w-quads.
    __shared__ float sx[CC][KH][SROW];  // 4080 B, rows 16B-aligned (68*4=272B)

    const int wq = threadIdx.x & 15;      // which float4 quad within tile
    const int u  = threadIdx.x >> 4;      // 0..15
    const int wb = blockIdx.x * TILE_W;   // tile base in w
    const int h  = blockIdx.y;
    const int n  = blockIdx.z;

    // ---- fill shared x tile (3 channels x 5 rows x 68 cols, zero-padded) ----
    for (int e = threadIdx.x; e < CC * KH * SROW; e += 256) {
        int pos = e % SROW;
        int t   = e / SROW;
        int i   = t % KH;
        int c   = t / KH;
        int col = wb + pos - 2;
        int row = h + i - 2;
        float v = 0.0f;
        if ((unsigned)col < WW && (unsigned)row < HH)
            v = x[((n * CC + c) * HH + row) * WW + col];
        sx[c][i][pos] = v;
    }
    __syncthreads();

    float4 acc0 = make_float4(0.f, 0.f, 0.f, 0.f);
    float4 acc1 = acc0;
    float4 acc2 = acc0;

    const int w0 = wb + wq * 4;
    // filters index (n, p=0, u, h, w0), viewed as float4
    const float4* fbase = reinterpret_cast<const float4*>(
        filters + ((((size_t)n * PP) * UU + u) * HH + h) * WW + w0);
    const size_t pstride4 = (size_t)UU * HH * WW / 4;  // float4 stride between p

    #pragma unroll
    for (int i = 0; i < KH; ++i) {
        // 5 filter float4 loads for this kernel row (streaming, bypass L2 persist)
        float4 f[KW];
        #pragma unroll
        for (int j = 0; j < KW; ++j)
            f[j] = __ldcs(fbase + (size_t)(i * KW + j) * pstride4);

        #pragma unroll
        for (int c = 0; c < CC; ++c) {
            // 8 patch values at positions wq*4 .. wq*4+7 : two aligned LDS.128
            const float4 a = *reinterpret_cast<const float4*>(&sx[c][i][wq * 4]);
            const float4 b = *reinterpret_cast<const float4*>(&sx[c][i][wq * 4 + 4]);
            const float pr[8] = {a.x, a.y, a.z, a.w, b.x, b.y, b.z, b.w};
            float4* acc = (c == 0) ? &acc0 : (c == 1) ? &acc1 : &acc2;
            #pragma unroll
            for (int j = 0; j < KW; ++j) {
                acc->x = fmaf(pr[j + 0], f[j].x, acc->x);
                acc->y = fmaf(pr[j + 1], f[j].y, acc->y);
                acc->z = fmaf(pr[j + 2], f[j].z, acc->z);
                acc->w = fmaf(pr[j + 3], f[j].w, acc->w);
            }
        }
    }

    // ---- store: out[n, c*16+u, h, w0..w0+3] ----
    #pragma unroll
    for (int c = 0; c < CC; ++c) {
        float4 v = (c == 0) ? acc0 : (c == 1) ? acc1 : acc2;
        float4* optr = reinterpret_cast<float4*>(
            out + ((((size_t)n * (CC * UU)) + c * UU + u) * HH + h) * WW + w0);
        __stcs(optr, v);
    }
}

extern "C" void kernel_launch(void* const* d_in, const int* in_sizes, int n_in,
                              void* d_out, int out_size) {
    const float* x       = (const float*)d_in[0];
    const float* filters = (const float*)d_in[1];
    float* out           = (float*)d_out;

    dim3 grid(WW / TILE_W, HH, NN);  // (5, 180, 4) = 3600 blocks
    dim3 block(256);
    duf_kernel<<<grid, block>>>(x, filters, out);
}

// round 2
// speedup vs baseline: 1.0532x; 1.0532x over previous
#include <cuda_runtime.h>

// DynamicUpsamplingFilter:
//   x:       (4, 3, 180, 320) f32
//   filters: (4, 25, 16, 180, 320) f32
//   out:     (4, 48, 180, 320) f32
//   out[n, c*16+u, h, w] = sum_p x_pad[n, c, h+p/5-2, w+p%5-2] * filters[n, p, u, h, w]

#define NN 4
#define CC 3
#define HH 180
#define WW 320
#define UU 16
#define KH 5
#define KW 5
#define PP (KH*KW)
#define TILE_W 64
#define SROW 68   // TILE_W + 4 (halo)

__global__ void __launch_bounds__(256, 4)
duf_kernel(const float* __restrict__ x,
           const float* __restrict__ filters,
           float* __restrict__ out) {
    // Block: one (n, h, w-tile of 64). 256 threads = 16 u-values x 16 w-quads.
    __shared__ float sx[CC][KH][SROW];  // 4080 B

    const int wq = threadIdx.x & 15;      // float4 quad within tile
    const int u  = threadIdx.x >> 4;      // 0..15
    const int wb = blockIdx.x * TILE_W;
    const int h  = blockIdx.y;
    const int n  = blockIdx.z;

    // ---- fill shared x tile (3 channels x 5 rows x 68 cols, zero-padded) ----
    for (int e = threadIdx.x; e < CC * KH * SROW; e += 256) {
        int pos = e % SROW;
        int t   = e / SROW;
        int i   = t % KH;
        int c   = t / KH;
        int col = wb + pos - 2;
        int row = h + i - 2;
        float v = 0.0f;
        if ((unsigned)col < WW && (unsigned)row < HH)
            v = x[((n * CC + c) * HH + row) * WW + col];
        sx[c][i][pos] = v;
    }
    __syncthreads();

    const int w0 = wb + wq * 4;
    const float* fp = filters + ((((size_t)n * PP) * UU + u) * HH + h) * WW + w0;
    const size_t PS = (size_t)UU * HH * WW;  // element stride between p planes

    // ---- software pipeline: double-buffer one kernel-row of filter loads ----
    float4 cur[KW], nxt[KW];
    #pragma unroll
    for (int j = 0; j < KW; ++j)
        cur[j] = __ldcs(reinterpret_cast<const float4*>(fp + (size_t)j * PS));

    float4 acc[CC];
    #pragma unroll
    for (int c = 0; c < CC; ++c) acc[c] = make_float4(0.f, 0.f, 0.f, 0.f);

    #pragma unroll
    for (int i = 0; i < KH; ++i) {
        // prefetch row i+1 while row i computes
        if (i < KH - 1) {
            #pragma unroll
            for (int j = 0; j < KW; ++j)
                nxt[j] = __ldcs(reinterpret_cast<const float4*>(
                    fp + (size_t)((i + 1) * KW + j) * PS));
        }

        #pragma unroll
        for (int c = 0; c < CC; ++c) {
            const float4 a = *reinterpret_cast<const float4*>(&sx[c][i][wq * 4]);
            const float4 b = *reinterpret_cast<const float4*>(&sx[c][i][wq * 4 + 4]);
            const float pr[8] = {a.x, a.y, a.z, a.w, b.x, b.y, b.z, b.w};
            #pragma unroll
            for (int j = 0; j < KW; ++j) {
                acc[c].x = fmaf(pr[j + 0], cur[j].x, acc[c].x);
                acc[c].y = fmaf(pr[j + 1], cur[j].y, acc[c].y);
                acc[c].z = fmaf(pr[j + 2], cur[j].z, acc[c].z);
                acc[c].w = fmaf(pr[j + 3], cur[j].w, acc[c].w);
            }
        }

        if (i < KH - 1) {
            #pragma unroll
            for (int j = 0; j < KW; ++j) cur[j] = nxt[j];
        }
    }

    // ---- store: out[n, c*16+u, h, w0..w0+3] ----
    #pragma unroll
    for (int c = 0; c < CC; ++c) {
        float4* optr = reinterpret_cast<float4*>(
            out + ((((size_t)n * (CC * UU)) + c * UU + u) * HH + h) * WW + w0);
        __stcs(optr, acc[c]);
    }
}

extern "C" void kernel_launch(void* const* d_in, const int* in_sizes, int n_in,
                              void* d_out, int out_size) {
    const float* x       = (const float*)d_in[0];
    const float* filters = (const float*)d_in[1];
    float* out           = (float*)d_out;

    dim3 grid(WW / TILE_W, HH, NN);  // (5, 180, 4) = 3600 blocks
    dim3 block(256);
    duf_kernel<<<grid, block>>>(x, filters, out);
}